// round 11
// baseline (speedup 1.0000x reference)
#include <cuda_runtime.h>

#define MM 4
#define LL 2
#define NSTATE 1296       // 6^4
#define SPAD 1332         // padded: 36 blocks of 37 float2
#define PTOT 2048
#define DD 64
#define NS 2              // states per CTA
#define TPB 192           // 96 per parity half; 72 active per half
#define TPS 72

// packed block-diagonal BS gates: blocks n=0..10, sizes 1..6..1, padded to 4 floats
__device__ __align__(16) float  g_BSp[12][164];
__device__ __align__(16) float2 g_U1c[LL][2][MM][36];  // folded complex 6x6 (SQ/DP)

__host__ __device__ __forceinline__ constexpr int OFFT(int n) {
    return n==0?0 : n==1?4 : n==2?8 : n==3?20 : n==4?36 : n==5?64
         : n==6?100 : n==7?128 : n==8?144 : n==9?156 : 160;
}

// =======================================================================
// Precompute (ONE block, one thread per small matrix):
//  - 132 threads: BS gate g, photon-number block n -> sb x sb expm (sb<=6)
//  - 16 threads: 6x6 SQ/DP expm with rot/kerr phases folded (complex out).
// expm via scaling (2^-5) + 10-term Taylor + 5 squarings.
// =======================================================================
__global__ void precompute_kernel(const float* __restrict__ bs1,
                                  const float* __restrict__ sq_r,
                                  const float* __restrict__ bs2,
                                  const float* __restrict__ disp,
                                  const float* __restrict__ rot1,
                                  const float* __restrict__ rot2,
                                  const float* __restrict__ kerr)
{
    int t = threadIdx.x;
    float A[6][6], P[6][6], T[6][6];

    if (t < 132) {
        int g = t / 11, n = t % 11;
        int l = g / 6, half = (g % 6) / 3, m = g % 3;
        float theta = (half ? bs2 : bs1)[l * 3 + m];
        const int sb = (n < 6) ? (n + 1) : (11 - n);
        const int am = (n < 6) ? 0 : (n - 5);
        #pragma unroll
        for (int r = 0; r < 6; r++) {
            #pragma unroll
            for (int c = 0; c < 6; c++) {
                float gg = 0.f;
                if (r < sb && c < sb) {
                    int R = 5 * (am + r) + n, Cc = 5 * (am + c) + n;
                    int i1 = R / 6, i2 = R % 6, j1 = Cc / 6, j2 = Cc % 6;
                    if (i1 == j1 + 1 && j2 == i2 + 1) gg += sqrtf((float)((j1 + 1) * (i2 + 1)));
                    if (j1 == i1 + 1 && i2 == j2 + 1) gg -= sqrtf((float)((i1 + 1) * (j2 + 1)));
                }
                float a = theta * gg * (1.f / 32.f);
                A[r][c] = a; P[r][c] = a; T[r][c] = a + (r == c ? 1.f : 0.f);
            }
        }
        for (int j = 2; j <= 10; j++) {
            float inv = 1.f / (float)j;
            float Pn[6][6];
            #pragma unroll
            for (int r = 0; r < 6; r++)
                #pragma unroll
                for (int c = 0; c < 6; c++) {
                    float s = 0.f;
                    #pragma unroll
                    for (int k = 0; k < 6; k++) s += P[r][k] * A[k][c];
                    Pn[r][c] = s * inv;
                }
            #pragma unroll
            for (int r = 0; r < 6; r++)
                #pragma unroll
                for (int c = 0; c < 6; c++) { P[r][c] = Pn[r][c]; T[r][c] += Pn[r][c]; }
        }
        for (int s = 0; s < 5; s++) {
            float Tn[6][6];
            #pragma unroll
            for (int r = 0; r < 6; r++)
                #pragma unroll
                for (int c = 0; c < 6; c++) {
                    float acc = 0.f;
                    #pragma unroll
                    for (int k = 0; k < 6; k++) acc += T[r][k] * T[k][c];
                    Tn[r][c] = acc;
                }
            #pragma unroll
            for (int r = 0; r < 6; r++)
                #pragma unroll
                for (int c = 0; c < 6; c++) T[r][c] = Tn[r][c];
        }
        int off = OFFT(n);
        #pragma unroll
        for (int ro = 0; ro < 6; ro++)
            #pragma unroll
            for (int ci = 0; ci < 6; ci++)
                if (ro < sb && ci < sb)
                    g_BSp[g][off + ci * sb + ro] = T[ro][ci];
    } else if (t < 148) {
        int mid = t - 132;
        int l = (mid % 8) / 4, m = mid % 4;
        float theta;
        if (mid < 8) theta = sq_r[l * 4 + m];
        else         theta = disp[l * 4 + m];
        #pragma unroll
        for (int r = 0; r < 6; r++) {
            #pragma unroll
            for (int c = 0; c < 6; c++) {
                float gg = 0.f;
                if (mid < 8) {
                    if (c == r + 2)      gg =  0.5f * sqrtf((float)((r + 1) * (r + 2)));
                    else if (r == c + 2) gg = -0.5f * sqrtf((float)((c + 1) * (c + 2)));
                } else {
                    if (r == c + 1)      gg =  sqrtf((float)(c + 1));
                    else if (c == r + 1) gg = -sqrtf((float)(r + 1));
                }
                float a = theta * gg * (1.f / 32.f);
                A[r][c] = a; P[r][c] = a; T[r][c] = a + (r == c ? 1.f : 0.f);
            }
        }
        for (int j = 2; j <= 10; j++) {
            float inv = 1.f / (float)j;
            float Pn[6][6];
            #pragma unroll
            for (int r = 0; r < 6; r++)
                #pragma unroll
                for (int c = 0; c < 6; c++) {
                    float s = 0.f;
                    #pragma unroll
                    for (int k = 0; k < 6; k++) s += P[r][k] * A[k][c];
                    Pn[r][c] = s * inv;
                }
            #pragma unroll
            for (int r = 0; r < 6; r++)
                #pragma unroll
                for (int c = 0; c < 6; c++) { P[r][c] = Pn[r][c]; T[r][c] += Pn[r][c]; }
        }
        for (int s = 0; s < 5; s++) {
            float Tn[6][6];
            #pragma unroll
            for (int r = 0; r < 6; r++)
                #pragma unroll
                for (int c = 0; c < 6; c++) {
                    float acc = 0.f;
                    #pragma unroll
                    for (int k = 0; k < 6; k++) acc += T[r][k] * T[k][c];
                    Tn[r][c] = acc;
                }
            #pragma unroll
            for (int r = 0; r < 6; r++)
                #pragma unroll
                for (int c = 0; c < 6; c++) T[r][c] = Tn[r][c];
        }
        #pragma unroll
        for (int r = 0; r < 6; r++) {
            #pragma unroll
            for (int c = 0; c < 6; c++) {
                float ang, sn, cs;
                if (mid < 8) {   // SQc = SQ @ diag(e^{i rot1 c})
                    ang = rot1[l * 4 + m] * (float)c;
                    sincosf(ang, &sn, &cs);
                    g_U1c[l][0][m][r * 6 + c] = make_float2(T[r][c] * cs, T[r][c] * sn);
                } else {         // DPc = diag(e^{i kerr r^2}) @ DP @ diag(e^{i rot2 c})
                    ang = kerr[l * 4 + m] * (float)(r * r) + rot2[l * 4 + m] * (float)c;
                    sincosf(ang, &sn, &cs);
                    g_U1c[l][1][m][r * 6 + c] = make_float2(T[r][c] * cs, T[r][c] * sn);
                }
            }
        }
    }
}

// =======================================================================
// Main kernel: NS states per CTA, 72 active threads/state.
// Parity halves are WARP-ALIGNED (boundary at tid 96): no warp executes
// both apply2 parity variants.
// =======================================================================

template<int S, int PAR>
__device__ __forceinline__ void apply2_blk(const float* __restrict__ pk,
                                           float2* __restrict__ st, int j)
{
    int baseP;
    if (S == 36)     baseP = j;
    else if (S == 6) baseP = (j / 6) * 222 + (j % 6);
    else             baseP = j * 37;

    #pragma unroll
    for (int n = PAR; n < 11; n += 2) {
        const int sb = (n < 6) ? (n + 1) : (11 - n);
        const int am = (n < 6) ? 0 : (n - 5);
        const int off = OFFT(n);
        float u[36];
        #pragma unroll
        for (int q = 0; q < (sb * sb + 3) / 4; q++) {
            float4 v = *(const float4*)(pk + off + 4 * q);
            u[4*q+0] = v.x; u[4*q+1] = v.y; u[4*q+2] = v.z; u[4*q+3] = v.w;
        }
        float2 x[6];
        #pragma unroll
        for (int a = 0; a < sb; a++) {
            const int R = 5 * (am + a) + n;
            const int o = (S == 36) ? R * 37 : (S == 6) ? (R * 6 + R / 6) : R;
            x[a] = st[baseP + o];
        }
        #pragma unroll
        for (int ao = 0; ao < sb; ao++) {
            float ar = 0.f, ai = 0.f;
            #pragma unroll
            for (int aiI = 0; aiI < sb; aiI++) {
                float uv = u[aiI * sb + ao];
                ar = fmaf(uv, x[aiI].x, ar);
                ai = fmaf(uv, x[aiI].y, ai);
            }
            const int R = 5 * (am + ao) + n;
            const int o = (S == 36) ? R * 37 : (S == 6) ? (R * 6 + R / 6) : R;
            st[baseP + o] = make_float2(ar, ai);
        }
    }
}

// complex 6x6 single-mode gate, 3 fibers per thread (72 threads/state), in-place
template<int m>
__device__ __forceinline__ void apply1c_mode(const float2* __restrict__ Uc,
                                             float2* __restrict__ st, int ft)
{
    const int KS = (m == 0) ? 222 : (m == 1) ? 37 : (m == 2) ? 6 : 1;
    int A0[3];
    float2 x[3][6];
    #pragma unroll
    for (int q = 0; q < 3; q++) {
        int f = ft + 72 * q;
        int a0;
        if (m == 0)      a0 = f + f / 36;
        else if (m == 1) a0 = (f / 36) * 222 + (f % 36);
        else if (m == 2) a0 = (f / 6) * 37 + (f % 6);
        else             a0 = (f / 6) * 37 + (f % 6) * 6;
        A0[q] = a0;
        #pragma unroll
        for (int k = 0; k < 6; k++) x[q][k] = st[a0 + k * KS];
    }
    #pragma unroll
    for (int r = 0; r < 6; r++) {
        float4 v0 = *(const float4*)((const float*)Uc + r * 12);
        float4 v1 = *(const float4*)((const float*)Uc + r * 12 + 4);
        float4 v2 = *(const float4*)((const float*)Uc + r * 12 + 8);
        float2 u[6];
        u[0] = make_float2(v0.x, v0.y); u[1] = make_float2(v0.z, v0.w);
        u[2] = make_float2(v1.x, v1.y); u[3] = make_float2(v1.z, v1.w);
        u[4] = make_float2(v2.x, v2.y); u[5] = make_float2(v2.z, v2.w);
        #pragma unroll
        for (int q = 0; q < 3; q++) {
            float ar = 0.f, ai = 0.f;
            #pragma unroll
            for (int k = 0; k < 6; k++) {
                ar = fmaf(u[k].x, x[q][k].x, ar); ar = fmaf(-u[k].y, x[q][k].y, ar);
                ai = fmaf(u[k].x, x[q][k].y, ai); ai = fmaf( u[k].y, x[q][k].x, ai);
            }
            st[A0[q] + r * KS] = make_float2(ar, ai);
        }
    }
}

extern __shared__ __align__(16) float2 sSt[];   // [NS][SPAD] -- state only

__global__ __launch_bounds__(TPB, 5) void qnn_kernel(const float* __restrict__ patches,
                                                     const float* __restrict__ enc_w,
                                                     const float* __restrict__ enc_b,
                                                     const float* __restrict__ ro_w,
                                                     const float* __restrict__ ro_b,
                                                     float* __restrict__ out)
{
    __shared__ __align__(16) float  sPk[2][164];
    __shared__ __align__(16) float2 sU1c[576];
    __shared__ float sAlpha[NS][4];
    __shared__ float sD0[NS][4][6];
    __shared__ float sPart[NS * 4][TPS];
    __shared__ float sRed[NS * 4][9];
    __shared__ float sQ[NS][4];

    int tid = threadIdx.x;
    int p0 = blockIdx.x * NS;
    // WARP-ALIGNED parity: tids [0,96) = par0, [96,192) = par1.
    int par = (tid >= 96) ? 1 : 0;
    int h   = tid - par * 96;
    bool act = h < 72;                 // 72 active per half, 24 idle
    int s = h / 36, j = h - s * 36;    // state, fiber column
    int ft = j + par * 36;             // per-state thread index 0..71
    float2* stS = sSt + s * SPAD;

    // stage BS gate 0 + all folded 6x6 gates (one-time)
    for (int i = tid; i < 41; i += TPB)
        ((float4*)sPk[0])[i] = __ldg((const float4*)g_BSp[0] + i);
    for (int i = tid; i < 288; i += TPB)
        ((float4*)sU1c)[i] = __ldg((const float4*)g_U1c + i);

    // alpha[s][m] = patches_row . enc_w^T + enc_b
    {
        int w = tid >> 5, lane = tid & 31;
        if (w < 4) {
            for (int task = w; task < 8; task += 4) {
                int ss = task >> 2, m = task & 3;
                const float* pr = patches + (size_t)(p0 + ss) * 64;
                float v = pr[lane] * enc_w[m * 64 + lane]
                        + pr[lane + 32] * enc_w[m * 64 + lane + 32];
                #pragma unroll
                for (int o = 16; o; o >>= 1) v += __shfl_xor_sync(0xffffffffu, v, o);
                if (lane == 0) sAlpha[ss][m] = v + enc_b[m];
            }
        }
    }
    __syncthreads();

    // Denc vacuum column: expm(alpha*(ad-a)) e0, 28-term Taylor (truncated gen)
    if (tid < 8) {
        int ss = tid >> 2, m = tid & 3;
        float al = sAlpha[ss][m];
        const float S1 = 1.f, S2 = 1.41421356f, S3 = 1.73205081f,
                    S4 = 2.f, S5 = 2.23606798f;
        float v0=1,v1=0,v2=0,v3=0,v4=0,v5=0;
        float t0=1,t1=0,t2=0,t3=0,t4=0,t5=0;
        for (int k = 1; k <= 28; k++) {
            float ik = al / (float)k;
            float n0 = ik * (          - S1 * t1);
            float n1 = ik * (S1 * t0 - S2 * t2);
            float n2 = ik * (S2 * t1 - S3 * t3);
            float n3 = ik * (S3 * t2 - S4 * t4);
            float n4 = ik * (S4 * t3 - S5 * t5);
            float n5 = ik * (S5 * t4);
            t0=n0; t1=n1; t2=n2; t3=n3; t4=n4; t5=n5;
            v0+=n0; v1+=n1; v2+=n2; v3+=n3; v4+=n4; v5+=n5;
        }
        sD0[ss][m][0]=v0; sD0[ss][m][1]=v1; sD0[ss][m][2]=v2;
        sD0[ss][m][3]=v3; sD0[ss][m][4]=v4; sD0[ss][m][5]=v5;
    }
    __syncthreads();

    // init state = outer product (real); each active thread fills 18 elements
    if (act) {
        float a01 = sD0[s][0][j / 6] * sD0[s][1][j % 6];
        int k0 = par * 18;
        #pragma unroll
        for (int k = 0; k < 18; k++) {
            int kk = k0 + k;
            stS[37 * j + kk] =
                make_float2(a01 * sD0[s][2][kk / 6] * sD0[s][3][kk % 6], 0.f);
        }
    }

    // GATE2(K): sync; stage BS gate K+1 into other buffer; apply BS gate K.
    #define GATE2(K, SS)                                                          \
        __syncthreads();                                                          \
        if ((K) < 11) {                                                           \
            for (int i = tid; i < 41; i += TPB)                                   \
                ((float4*)sPk[((K)+1)&1])[i] =                                    \
                    __ldg((const float4*)g_BSp[(K)+1] + i);                       \
        }                                                                         \
        if (act) {                                                                \
            if (par == 0) apply2_blk<SS,0>(sPk[(K)&1], stS, j);                   \
            else          apply2_blk<SS,1>(sPk[(K)&1], stS, j);                   \
        }

    for (int hh = 0; hh < 4; hh++) {
        int kg = 3 * hh;
        GATE2(kg, 36)
        GATE2(kg + 1, 6)
        GATE2(kg + 2, 1)
        const float2* P1 = sU1c + hh * 144;   // SQ(l0), DP(l0), SQ(l1), DP(l1)
        __syncthreads(); if (act) apply1c_mode<0>(P1,       stS, ft);
        __syncthreads(); if (act) apply1c_mode<1>(P1 + 36,  stS, ft);
        __syncthreads(); if (act) apply1c_mode<2>(P1 + 72,  stS, ft);
        __syncthreads(); if (act) apply1c_mode<3>(P1 + 108, stS, ft);
    }

    // quadrature expectations
    __syncthreads();
    if (act) {
        const float W[5] = {2.f, 2.82842712f, 3.46410162f, 4.f, 4.47213595f};
        int n0 = j / 6, n1 = j % 6;
        float q0 = 0.f, q1 = 0.f, q2 = 0.f, q3 = 0.f;
        int k0 = par * 18;
        #pragma unroll
        for (int k = 0; k < 18; k++) {
            int kk = k0 + k;
            int base = 37 * j + kk;
            float2 s0 = stS[base];
            if (n0 < 5)     { float2 sN = stS[base + 222]; q0 += s0.x * sN.x + s0.y * sN.y; }
            if (n1 < 5)     { float2 sN = stS[base + 37];  q1 += s0.x * sN.x + s0.y * sN.y; }
            if (kk / 6 < 5) { float2 sN = stS[base + 6];   q2 += W[kk / 6] * (s0.x * sN.x + s0.y * sN.y); }
            if (kk % 6 < 5) { float2 sN = stS[base + 1];   q3 += W[kk % 6] * (s0.x * sN.x + s0.y * sN.y); }
        }
        if (n0 < 5) q0 *= W[n0];
        if (n1 < 5) q1 *= W[n1];
        sPart[s * 4 + 0][ft] = q0; sPart[s * 4 + 1][ft] = q1;
        sPart[s * 4 + 2][ft] = q2; sPart[s * 4 + 3][ft] = q3;
    }
    __syncthreads();
    // two-stage reduction
    if (tid < 72) {
        int row = tid / 9, col = tid % 9;
        float acc = 0.f;
        #pragma unroll
        for (int k = 0; k < 8; k++) acc += sPart[row][col * 8 + k];
        sRed[row][col] = acc;
    }
    __syncthreads();
    if (tid < 8) {
        float acc = 0.f;
        #pragma unroll
        for (int k = 0; k < 9; k++) acc += sRed[tid][k];
        sQ[tid >> 2][tid & 3] = acc;
    }
    __syncthreads();

    // readout
    if (tid < NS * DD) {
        int ss = tid >> 6, d = tid & 63;
        float o = ro_b[d];
        #pragma unroll
        for (int m = 0; m < 4; m++) o = fmaf(sQ[ss][m], ro_w[d * 4 + m], o);
        out[(size_t)(p0 + ss) * DD + d] = o;
    }
}

// =======================================================================
extern "C" void kernel_launch(void* const* d_in, const int* in_sizes, int n_in,
                              void* d_out, int out_size)
{
    const float* patches = (const float*)d_in[0];
    const float* enc_w   = (const float*)d_in[1];
    const float* enc_b   = (const float*)d_in[2];
    const float* bs1     = (const float*)d_in[3];
    const float* rot1    = (const float*)d_in[4];
    const float* sq_r    = (const float*)d_in[5];
    const float* bs2     = (const float*)d_in[6];
    const float* rot2    = (const float*)d_in[7];
    const float* disp    = (const float*)d_in[8];
    const float* kerr    = (const float*)d_in[9];
    const float* ro_w    = (const float*)d_in[10];
    const float* ro_b    = (const float*)d_in[11];

    precompute_kernel<<<1, 148>>>(bs1, sq_r, bs2, disp, rot1, rot2, kerr);
    qnn_kernel<<<PTOT / NS, TPB, NS * SPAD * sizeof(float2)>>>(
        patches, enc_w, enc_b, ro_w, ro_b, (float*)d_out);
}

// round 14
// speedup vs baseline: 1.5469x; 1.5469x over previous
#include <cuda_runtime.h>

#define NS 4
#define TPB 144
#define PTOT 2048
#define DD 64
#define SPAD 1332   // 36 tiles * 37 float2

__device__ __align__(16) float  g_BSp[12][164];
__device__ __align__(16) float  g_U1r[4][4][36];    // [set][mode] real 6x6
__device__ __align__(16) float2 g_Ph[4][2][2][36];  // [set][pre/post][01/23][36]

__host__ __device__ __forceinline__ constexpr int OFFT(int n) {
    return n==0?0 : n==1?4 : n==2?8 : n==3?20 : n==4?36 : n==5?64
         : n==6?100 : n==7?128 : n==8?144 : n==9?156 : 160;
}

// =======================================================================
// Precompute: ONE block of 148 threads (register-budget-safe).
// 132 thr: BS blocks; 16 thr: real 6x6 SQ/DP expm; then ALL threads
// grid-stride the 576 phase-table entries.
// =======================================================================
__global__ void precompute_kernel(const float* __restrict__ bs1,
                                  const float* __restrict__ sq_r,
                                  const float* __restrict__ bs2,
                                  const float* __restrict__ disp,
                                  const float* __restrict__ rot1,
                                  const float* __restrict__ rot2,
                                  const float* __restrict__ kerr)
{
    int t = threadIdx.x;
    float A[6][6], P[6][6], T[6][6];

    if (t < 132) {
        int g = t / 11, n = t % 11;
        int l = g / 6, half = (g % 6) / 3, m = g % 3;
        float theta = (half ? bs2 : bs1)[l * 3 + m];
        const int sb = (n < 6) ? (n + 1) : (11 - n);
        const int am = (n < 6) ? 0 : (n - 5);
        #pragma unroll
        for (int r = 0; r < 6; r++)
            #pragma unroll
            for (int c = 0; c < 6; c++) {
                float gg = 0.f;
                if (r < sb && c < sb) {
                    int R = 5 * (am + r) + n, Cc = 5 * (am + c) + n;
                    int i1 = R / 6, i2 = R % 6, j1 = Cc / 6, j2 = Cc % 6;
                    if (i1 == j1 + 1 && j2 == i2 + 1) gg += sqrtf((float)((j1 + 1) * (i2 + 1)));
                    if (j1 == i1 + 1 && i2 == j2 + 1) gg -= sqrtf((float)((i1 + 1) * (j2 + 1)));
                }
                float a = theta * gg * (1.f / 32.f);
                A[r][c] = a; P[r][c] = a; T[r][c] = a + (r == c ? 1.f : 0.f);
            }
        for (int j = 2; j <= 10; j++) {
            float inv = 1.f / (float)j;
            float Pn[6][6];
            #pragma unroll
            for (int r = 0; r < 6; r++)
                #pragma unroll
                for (int c = 0; c < 6; c++) {
                    float s = 0.f;
                    #pragma unroll
                    for (int k = 0; k < 6; k++) s += P[r][k] * A[k][c];
                    Pn[r][c] = s * inv;
                }
            #pragma unroll
            for (int r = 0; r < 6; r++)
                #pragma unroll
                for (int c = 0; c < 6; c++) { P[r][c] = Pn[r][c]; T[r][c] += Pn[r][c]; }
        }
        for (int s = 0; s < 5; s++) {
            float Tn[6][6];
            #pragma unroll
            for (int r = 0; r < 6; r++)
                #pragma unroll
                for (int c = 0; c < 6; c++) {
                    float acc = 0.f;
                    #pragma unroll
                    for (int k = 0; k < 6; k++) acc += T[r][k] * T[k][c];
                    Tn[r][c] = acc;
                }
            #pragma unroll
            for (int r = 0; r < 6; r++)
                #pragma unroll
                for (int c = 0; c < 6; c++) T[r][c] = Tn[r][c];
        }
        int off = OFFT(n);
        #pragma unroll
        for (int ro = 0; ro < 6; ro++)
            #pragma unroll
            for (int ci = 0; ci < 6; ci++)
                if (ro < sb && ci < sb)
                    g_BSp[g][off + ci * sb + ro] = T[ro][ci];
    } else if (t < 148) {
        int mid = t - 132;
        int l = (mid % 8) / 4, m = mid % 4;
        float theta = (mid < 8) ? sq_r[l * 4 + m] : disp[l * 4 + m];
        #pragma unroll
        for (int r = 0; r < 6; r++)
            #pragma unroll
            for (int c = 0; c < 6; c++) {
                float gg = 0.f;
                if (mid < 8) {
                    if (c == r + 2)      gg =  0.5f * sqrtf((float)((r + 1) * (r + 2)));
                    else if (r == c + 2) gg = -0.5f * sqrtf((float)((c + 1) * (c + 2)));
                } else {
                    if (r == c + 1)      gg =  sqrtf((float)(c + 1));
                    else if (c == r + 1) gg = -sqrtf((float)(r + 1));
                }
                float a = theta * gg * (1.f / 32.f);
                A[r][c] = a; P[r][c] = a; T[r][c] = a + (r == c ? 1.f : 0.f);
            }
        for (int j = 2; j <= 10; j++) {
            float inv = 1.f / (float)j;
            float Pn[6][6];
            #pragma unroll
            for (int r = 0; r < 6; r++)
                #pragma unroll
                for (int c = 0; c < 6; c++) {
                    float s = 0.f;
                    #pragma unroll
                    for (int k = 0; k < 6; k++) s += P[r][k] * A[k][c];
                    Pn[r][c] = s * inv;
                }
            #pragma unroll
            for (int r = 0; r < 6; r++)
                #pragma unroll
                for (int c = 0; c < 6; c++) { P[r][c] = Pn[r][c]; T[r][c] += Pn[r][c]; }
        }
        for (int s = 0; s < 5; s++) {
            float Tn[6][6];
            #pragma unroll
            for (int r = 0; r < 6; r++)
                #pragma unroll
                for (int c = 0; c < 6; c++) {
                    float acc = 0.f;
                    #pragma unroll
                    for (int k = 0; k < 6; k++) acc += T[r][k] * T[k][c];
                    Tn[r][c] = acc;
                }
            #pragma unroll
            for (int r = 0; r < 6; r++)
                #pragma unroll
                for (int c = 0; c < 6; c++) T[r][c] = Tn[r][c];
        }
        int set = l * 2 + (mid < 8 ? 0 : 1);   // SQ l0, DP l0, SQ l1, DP l1
        #pragma unroll
        for (int r = 0; r < 6; r++)
            #pragma unroll
            for (int c = 0; c < 6; c++)
                g_U1r[set][m][r * 6 + c] = T[r][c];
    }

    // phase tables: grid-stride over 576 entries with 148 threads
    for (int tt = t; tt < 576; tt += 148) {
        int s4 = tt / 144, r = tt % 144;
        int pp = r / 72, hl = (r / 36) % 2, k = r % 36;
        int l = s4 >> 1, isDP = s4 & 1;
        int na = k / 6, nb = k % 6;
        int ma = hl ? 2 : 0, mb = ma + 1;
        float ang = 0.f;
        if (pp == 0) {
            const float* th = isDP ? rot2 : rot1;
            ang = th[l * 4 + ma] * (float)na + th[l * 4 + mb] * (float)nb;
        } else if (isDP) {
            ang = kerr[l * 4 + ma] * (float)(na * na) + kerr[l * 4 + mb] * (float)(nb * nb);
        }
        float sn, cs;
        sincosf(ang, &sn, &cs);
        g_Ph[s4][pp][hl][k] = make_float2(cs, sn);
    }
}

// ======================= main kernel helpers =======================

__device__ __forceinline__ void bs_apply(const float* __restrict__ pk, float2* x)
{
    #pragma unroll
    for (int n = 0; n < 11; n++) {
        const int sb = (n < 6) ? (n + 1) : (11 - n);
        const int am = (n < 6) ? 0 : (n - 5);
        const int off = OFFT(n);
        float2 acc[6];
        #pragma unroll
        for (int a = 0; a < sb; a++) acc[a] = make_float2(0.f, 0.f);
        #pragma unroll
        for (int ai = 0; ai < sb; ai++) {
            float2 xi = x[5 * (am + ai) + n];
            #pragma unroll
            for (int ao = 0; ao < sb; ao++) {
                float u = pk[off + ai * sb + ao];
                acc[ao].x = fmaf(u, xi.x, acc[ao].x);
                acc[ao].y = fmaf(u, xi.y, acc[ao].y);
            }
        }
        #pragma unroll
        for (int ao = 0; ao < sb; ao++) x[5 * (am + ao) + n] = acc[ao];
    }
}

__device__ __forceinline__ void mode_fast(const float* __restrict__ u, float2* x)
{
    #pragma unroll
    for (int g = 0; g < 6; g++) {
        float2 y[6];
        #pragma unroll
        for (int r = 0; r < 6; r++) {
            const float2* ur = (const float2*)(u + r * 6);
            float2 a = ur[0], b = ur[1], c = ur[2];
            y[r].x = a.x*x[g*6+0].x + a.y*x[g*6+1].x + b.x*x[g*6+2].x
                   + b.y*x[g*6+3].x + c.x*x[g*6+4].x + c.y*x[g*6+5].x;
            y[r].y = a.x*x[g*6+0].y + a.y*x[g*6+1].y + b.x*x[g*6+2].y
                   + b.y*x[g*6+3].y + c.x*x[g*6+4].y + c.y*x[g*6+5].y;
        }
        #pragma unroll
        for (int r = 0; r < 6; r++) x[g*6+r] = y[r];
    }
}

__device__ __forceinline__ void mode_slow(const float* __restrict__ u, float2* x)
{
    #pragma unroll
    for (int g = 0; g < 6; g++) {
        float2 y[6];
        #pragma unroll
        for (int r = 0; r < 6; r++) {
            const float2* ur = (const float2*)(u + r * 6);
            float2 a = ur[0], b = ur[1], c = ur[2];
            y[r].x = a.x*x[0*6+g].x + a.y*x[1*6+g].x + b.x*x[2*6+g].x
                   + b.y*x[3*6+g].x + c.x*x[4*6+g].x + c.y*x[5*6+g].x;
            y[r].y = a.x*x[0*6+g].y + a.y*x[1*6+g].y + b.x*x[2*6+g].y
                   + b.y*x[3*6+g].y + c.x*x[4*6+g].y + c.y*x[5*6+g].y;
        }
        #pragma unroll
        for (int r = 0; r < 6; r++) x[r*6+g] = y[r];
    }
}

__device__ __forceinline__ void phase36(const float2* __restrict__ ph, float2* x)
{
    #pragma unroll
    for (int t = 0; t < 36; t++) {
        float2 p = ph[t], v = x[t];
        x[t] = make_float2(v.x*p.x - v.y*p.y, v.x*p.y + v.y*p.x);
    }
}

extern __shared__ __align__(16) float2 sSt[];   // [NS][SPAD]

__global__ __launch_bounds__(TPB, 4) void qnn_kernel(const float* __restrict__ patches,
                                                     const float* __restrict__ enc_w,
                                                     const float* __restrict__ enc_b,
                                                     const float* __restrict__ ro_w,
                                                     const float* __restrict__ ro_b,
                                                     float* __restrict__ out)
{
    __shared__ __align__(16) float  sPk[2][164];
    __shared__ __align__(16) float  sU1r[4][4][36];
    __shared__ __align__(16) float2 sPh[4][2][2][36];
    __shared__ float sAlpha[NS][4];
    __shared__ float sD0[NS][4][6];
    __shared__ float sPart[16][37];
    __shared__ float sRed[16][9];
    __shared__ float sQ[16];

    int tid = threadIdx.x;
    int p0 = blockIdx.x * NS;
    int s = tid / 36, j = tid % 36;
    float2* stS = sSt + s * SPAD;

    // one-time staging
    for (int i = tid; i < 41; i += TPB)
        ((float4*)sPk[0])[i] = __ldg((const float4*)g_BSp[0] + i);
    for (int i = tid; i < 144; i += TPB)
        ((float4*)sU1r)[i] = __ldg((const float4*)g_U1r + i);
    for (int i = tid; i < 288; i += TPB)
        ((float4*)sPh)[i] = __ldg((const float4*)g_Ph + i);

    // alpha
    {
        int w = tid >> 5, lane = tid & 31;
        if (w < 4) {
            for (int task = w; task < 16; task += 4) {
                int ss = task >> 2, m = task & 3;
                const float* pr = patches + (size_t)(p0 + ss) * 64;
                float v = pr[lane] * enc_w[m * 64 + lane]
                        + pr[lane + 32] * enc_w[m * 64 + lane + 32];
                #pragma unroll
                for (int o = 16; o; o >>= 1) v += __shfl_xor_sync(0xffffffffu, v, o);
                if (lane == 0) sAlpha[ss][m] = v + enc_b[m];
            }
        }
    }
    __syncthreads();

    // Denc vacuum columns
    if (tid < 16) {
        int ss = tid >> 2, m = tid & 3;
        float al = sAlpha[ss][m];
        const float S1=1.f, S2=1.41421356f, S3=1.73205081f, S4=2.f, S5=2.23606798f;
        float v0=1,v1=0,v2=0,v3=0,v4=0,v5=0;
        float t0=1,t1=0,t2=0,t3=0,t4=0,t5=0;
        for (int k = 1; k <= 28; k++) {
            float ik = al / (float)k;
            float n0 = ik * (          - S1 * t1);
            float n1 = ik * (S1 * t0 - S2 * t2);
            float n2 = ik * (S2 * t1 - S3 * t3);
            float n3 = ik * (S3 * t2 - S4 * t4);
            float n4 = ik * (S4 * t3 - S5 * t5);
            float n5 = ik * (S5 * t4);
            t0=n0;t1=n1;t2=n2;t3=n3;t4=n4;t5=n5;
            v0+=n0;v1+=n1;v2+=n2;v3+=n3;v4+=n4;v5+=n5;
        }
        sD0[ss][m][0]=v0; sD0[ss][m][1]=v1; sD0[ss][m][2]=v2;
        sD0[ss][m][3]=v3; sD0[ss][m][4]=v4; sD0[ss][m][5]=v5;
    }
    __syncthreads();

    float2 x[36];

    #define STG(K)                                                         \
        for (int i = tid; i < 41; i += TPB)                                \
            ((float4*)sPk[(K) & 1])[i] = __ldg((const float4*)g_BSp[K] + i);

    #pragma unroll 1
    for (int h = 0; h < 4; h++) {
        // ---- PASS A: tile (n0,n1); pending set h-1 mode 0,1 ops; BS01 ----
        if (h) __syncthreads();
        STG(3*h + 1)
        if (h == 0) {
            float c23 = sD0[s][2][j/6] * sD0[s][3][j%6];
            #pragma unroll
            for (int a = 0; a < 6; a++) {
                float va = sD0[s][0][a] * c23;
                #pragma unroll
                for (int b = 0; b < 6; b++)
                    x[a*6+b] = make_float2(va * sD0[s][1][b], 0.f);
            }
        } else {
            #pragma unroll
            for (int t = 0; t < 36; t++) x[t] = stS[t*37 + j];
            int hs = h - 1;
            phase36(&sPh[hs][0][0][0], x);
            mode_slow(sU1r[hs][0], x);
            mode_fast(sU1r[hs][1], x);
            if (hs & 1) phase36(&sPh[hs][1][0][0], x);
        }
        bs_apply(sPk[(3*h) & 1], x);
        #pragma unroll
        for (int t = 0; t < 36; t++) stS[t*37 + j] = x[t];
        __syncthreads();

        // ---- PASS B: tile (n1,n2); BS12 ----
        STG(3*h + 2)
        {
            int base = (j/6)*222 + (j%6);
            #pragma unroll
            for (int t = 0; t < 36; t++) x[t] = stS[base + (t/6)*37 + (t%6)*6];
            bs_apply(sPk[(3*h+1) & 1], x);
            #pragma unroll
            for (int t = 0; t < 36; t++) stS[base + (t/6)*37 + (t%6)*6] = x[t];
        }
        __syncthreads();

        // ---- PASS C: tile (n2,n3); BS23; set h mode 2,3 ops ----
        if (3*h + 3 < 12) { STG(3*h + 3) }
        {
            int base = j * 37;
            #pragma unroll
            for (int t = 0; t < 36; t++) x[t] = stS[base + t];
            bs_apply(sPk[(3*h+2) & 1], x);
            phase36(&sPh[h][0][1][0], x);
            mode_slow(sU1r[h][2], x);
            mode_fast(sU1r[h][3], x);
            if (h & 1) phase36(&sPh[h][1][1][0], x);
            #pragma unroll
            for (int t = 0; t < 36; t++) stS[base + t] = x[t];
        }
    }

    // ---- EPILOGUE: set 3 mode 0,1 ops; quadratures ----
    __syncthreads();
    #pragma unroll
    for (int t = 0; t < 36; t++) x[t] = stS[t*37 + j];
    phase36(&sPh[3][0][0][0], x);
    mode_slow(sU1r[3][0], x);
    mode_fast(sU1r[3][1], x);
    phase36(&sPh[3][1][0][0], x);

    const float W[5] = {2.f, 2.82842712f, 3.46410162f, 4.f, 4.47213595f};
    float q0 = 0.f, q1 = 0.f;
    #pragma unroll
    for (int a = 0; a < 6; a++)
        #pragma unroll
        for (int b = 0; b < 6; b++) {
            if (a < 5) q0 += W[a] * (x[a*6+b].x * x[(a+1)*6+b].x + x[a*6+b].y * x[(a+1)*6+b].y);
            if (b < 5) q1 += W[b] * (x[a*6+b].x * x[a*6+b+1].x + x[a*6+b].y * x[a*6+b+1].y);
        }
    #pragma unroll
    for (int t = 0; t < 36; t++) stS[t*37 + j] = x[t];
    __syncthreads();

    float q2 = 0.f, q3 = 0.f;
    {
        int n2 = j / 6, n3 = j % 6;
        #pragma unroll
        for (int t = 0; t < 36; t++) {
            int base = t*37 + j;
            float2 s0 = stS[base];
            if (n2 < 5) { float2 sN = stS[base + 6]; q2 += s0.x*sN.x + s0.y*sN.y; }
            if (n3 < 5) { float2 sN = stS[base + 1]; q3 += s0.x*sN.x + s0.y*sN.y; }
        }
        if (n2 < 5) q2 *= W[n2];
        if (n3 < 5) q3 *= W[n3];
    }
    sPart[s*4 + 0][j] = q0; sPart[s*4 + 1][j] = q1;
    sPart[s*4 + 2][j] = q2; sPart[s*4 + 3][j] = q3;
    __syncthreads();

    {
        int row = tid / 9, col = tid % 9;
        float acc = 0.f;
        #pragma unroll
        for (int k = 0; k < 4; k++) acc += sPart[row][col*4 + k];
        sRed[row][col] = acc;
    }
    __syncthreads();
    if (tid < 16) {
        float acc = 0.f;
        #pragma unroll
        for (int k = 0; k < 9; k++) acc += sRed[tid][k];
        sQ[tid] = acc;
    }
    __syncthreads();

    for (int idx = tid; idx < NS * DD; idx += TPB) {
        int ss = idx >> 6, d = idx & 63;
        float o = ro_b[d];
        #pragma unroll
        for (int m = 0; m < 4; m++) o = fmaf(sQ[ss*4 + m], ro_w[d*4 + m], o);
        out[(size_t)(p0 + ss) * DD + d] = o;
    }
}

extern "C" void kernel_launch(void* const* d_in, const int* in_sizes, int n_in,
                              void* d_out, int out_size)
{
    const float* patches = (const float*)d_in[0];
    const float* enc_w   = (const float*)d_in[1];
    const float* enc_b   = (const float*)d_in[2];
    const float* bs1     = (const float*)d_in[3];
    const float* rot1    = (const float*)d_in[4];
    const float* sq_r    = (const float*)d_in[5];
    const float* bs2     = (const float*)d_in[6];
    const float* rot2    = (const float*)d_in[7];
    const float* disp    = (const float*)d_in[8];
    const float* kerr    = (const float*)d_in[9];
    const float* ro_w    = (const float*)d_in[10];
    const float* ro_b    = (const float*)d_in[11];

    // opt-in for >48KB combined smem (static ~11.7KB + dynamic 42.6KB).
    static bool attr_set = false;
    if (!attr_set) {
        cudaFuncSetAttribute(qnn_kernel, cudaFuncAttributeMaxDynamicSharedMemorySize,
                             NS * SPAD * (int)sizeof(float2));
        attr_set = true;
    }

    precompute_kernel<<<1, 148>>>(bs1, sq_r, bs2, disp, rot1, rot2, kerr);
    qnn_kernel<<<PTOT / NS, TPB, NS * SPAD * sizeof(float2)>>>(
        patches, enc_w, enc_b, ro_w, ro_b, (float*)d_out);
}

// round 15
// speedup vs baseline: 1.6613x; 1.0740x over previous
#include <cuda_runtime.h>

#define MAXNS 5
#define TPB 180
#define GRID 444     // 3 * 148 SMs exactly; blocks 0..271 -> 5 states, rest -> 4
#define PTOT 2048
#define DD 64
#define SPAD 1332    // 36 tiles * 37 float2

__device__ __align__(16) float  g_BSp[12][164];
__device__ __align__(16) float  g_U1r[4][4][36];    // [set][mode] real 6x6
__device__ __align__(16) float2 g_Ph[4][2][2][36];  // [set][pre/post][01/23][36]

__host__ __device__ __forceinline__ constexpr int OFFT(int n) {
    return n==0?0 : n==1?4 : n==2?8 : n==3?20 : n==4?36 : n==5?64
         : n==6?100 : n==7?128 : n==8?144 : n==9?156 : 160;
}

// =======================================================================
// Precompute: ONE block of 148 threads.
// =======================================================================
__global__ void precompute_kernel(const float* __restrict__ bs1,
                                  const float* __restrict__ sq_r,
                                  const float* __restrict__ bs2,
                                  const float* __restrict__ disp,
                                  const float* __restrict__ rot1,
                                  const float* __restrict__ rot2,
                                  const float* __restrict__ kerr)
{
    int t = threadIdx.x;
    float A[6][6], P[6][6], T[6][6];

    if (t < 132) {
        int g = t / 11, n = t % 11;
        int l = g / 6, half = (g % 6) / 3, m = g % 3;
        float theta = (half ? bs2 : bs1)[l * 3 + m];
        const int sb = (n < 6) ? (n + 1) : (11 - n);
        const int am = (n < 6) ? 0 : (n - 5);
        #pragma unroll
        for (int r = 0; r < 6; r++)
            #pragma unroll
            for (int c = 0; c < 6; c++) {
                float gg = 0.f;
                if (r < sb && c < sb) {
                    int R = 5 * (am + r) + n, Cc = 5 * (am + c) + n;
                    int i1 = R / 6, i2 = R % 6, j1 = Cc / 6, j2 = Cc % 6;
                    if (i1 == j1 + 1 && j2 == i2 + 1) gg += sqrtf((float)((j1 + 1) * (i2 + 1)));
                    if (j1 == i1 + 1 && i2 == j2 + 1) gg -= sqrtf((float)((i1 + 1) * (j2 + 1)));
                }
                float a = theta * gg * (1.f / 32.f);
                A[r][c] = a; P[r][c] = a; T[r][c] = a + (r == c ? 1.f : 0.f);
            }
        for (int j = 2; j <= 10; j++) {
            float inv = 1.f / (float)j;
            float Pn[6][6];
            #pragma unroll
            for (int r = 0; r < 6; r++)
                #pragma unroll
                for (int c = 0; c < 6; c++) {
                    float s = 0.f;
                    #pragma unroll
                    for (int k = 0; k < 6; k++) s += P[r][k] * A[k][c];
                    Pn[r][c] = s * inv;
                }
            #pragma unroll
            for (int r = 0; r < 6; r++)
                #pragma unroll
                for (int c = 0; c < 6; c++) { P[r][c] = Pn[r][c]; T[r][c] += Pn[r][c]; }
        }
        for (int s = 0; s < 5; s++) {
            float Tn[6][6];
            #pragma unroll
            for (int r = 0; r < 6; r++)
                #pragma unroll
                for (int c = 0; c < 6; c++) {
                    float acc = 0.f;
                    #pragma unroll
                    for (int k = 0; k < 6; k++) acc += T[r][k] * T[k][c];
                    Tn[r][c] = acc;
                }
            #pragma unroll
            for (int r = 0; r < 6; r++)
                #pragma unroll
                for (int c = 0; c < 6; c++) T[r][c] = Tn[r][c];
        }
        int off = OFFT(n);
        #pragma unroll
        for (int ro = 0; ro < 6; ro++)
            #pragma unroll
            for (int ci = 0; ci < 6; ci++)
                if (ro < sb && ci < sb)
                    g_BSp[g][off + ci * sb + ro] = T[ro][ci];
    } else if (t < 148) {
        int mid = t - 132;
        int l = (mid % 8) / 4, m = mid % 4;
        float theta = (mid < 8) ? sq_r[l * 4 + m] : disp[l * 4 + m];
        #pragma unroll
        for (int r = 0; r < 6; r++)
            #pragma unroll
            for (int c = 0; c < 6; c++) {
                float gg = 0.f;
                if (mid < 8) {
                    if (c == r + 2)      gg =  0.5f * sqrtf((float)((r + 1) * (r + 2)));
                    else if (r == c + 2) gg = -0.5f * sqrtf((float)((c + 1) * (c + 2)));
                } else {
                    if (r == c + 1)      gg =  sqrtf((float)(c + 1));
                    else if (c == r + 1) gg = -sqrtf((float)(r + 1));
                }
                float a = theta * gg * (1.f / 32.f);
                A[r][c] = a; P[r][c] = a; T[r][c] = a + (r == c ? 1.f : 0.f);
            }
        for (int j = 2; j <= 10; j++) {
            float inv = 1.f / (float)j;
            float Pn[6][6];
            #pragma unroll
            for (int r = 0; r < 6; r++)
                #pragma unroll
                for (int c = 0; c < 6; c++) {
                    float s = 0.f;
                    #pragma unroll
                    for (int k = 0; k < 6; k++) s += P[r][k] * A[k][c];
                    Pn[r][c] = s * inv;
                }
            #pragma unroll
            for (int r = 0; r < 6; r++)
                #pragma unroll
                for (int c = 0; c < 6; c++) { P[r][c] = Pn[r][c]; T[r][c] += Pn[r][c]; }
        }
        for (int s = 0; s < 5; s++) {
            float Tn[6][6];
            #pragma unroll
            for (int r = 0; r < 6; r++)
                #pragma unroll
                for (int c = 0; c < 6; c++) {
                    float acc = 0.f;
                    #pragma unroll
                    for (int k = 0; k < 6; k++) acc += T[r][k] * T[k][c];
                    Tn[r][c] = acc;
                }
            #pragma unroll
            for (int r = 0; r < 6; r++)
                #pragma unroll
                for (int c = 0; c < 6; c++) T[r][c] = Tn[r][c];
        }
        int set = l * 2 + (mid < 8 ? 0 : 1);   // SQ l0, DP l0, SQ l1, DP l1
        #pragma unroll
        for (int r = 0; r < 6; r++)
            #pragma unroll
            for (int c = 0; c < 6; c++)
                g_U1r[set][m][r * 6 + c] = T[r][c];
    }

    // phase tables: grid-stride over 576 entries with 148 threads
    for (int tt = t; tt < 576; tt += 148) {
        int s4 = tt / 144, r = tt % 144;
        int pp = r / 72, hl = (r / 36) % 2, k = r % 36;
        int l = s4 >> 1, isDP = s4 & 1;
        int na = k / 6, nb = k % 6;
        int ma = hl ? 2 : 0, mb = ma + 1;
        float ang = 0.f;
        if (pp == 0) {
            const float* th = isDP ? rot2 : rot1;
            ang = th[l * 4 + ma] * (float)na + th[l * 4 + mb] * (float)nb;
        } else if (isDP) {
            ang = kerr[l * 4 + ma] * (float)(na * na) + kerr[l * 4 + mb] * (float)(nb * nb);
        }
        float sn, cs;
        sincosf(ang, &sn, &cs);
        g_Ph[s4][pp][hl][k] = make_float2(cs, sn);
    }
}

// ======================= main kernel helpers =======================

__device__ __forceinline__ void bs_apply(const float* __restrict__ pk, float2* x)
{
    #pragma unroll
    for (int n = 0; n < 11; n++) {
        const int sb = (n < 6) ? (n + 1) : (11 - n);
        const int am = (n < 6) ? 0 : (n - 5);
        const int off = OFFT(n);
        float2 acc[6];
        #pragma unroll
        for (int a = 0; a < sb; a++) acc[a] = make_float2(0.f, 0.f);
        #pragma unroll
        for (int ai = 0; ai < sb; ai++) {
            float2 xi = x[5 * (am + ai) + n];
            #pragma unroll
            for (int ao = 0; ao < sb; ao++) {
                float u = pk[off + ai * sb + ao];
                acc[ao].x = fmaf(u, xi.x, acc[ao].x);
                acc[ao].y = fmaf(u, xi.y, acc[ao].y);
            }
        }
        #pragma unroll
        for (int ao = 0; ao < sb; ao++) x[5 * (am + ao) + n] = acc[ao];
    }
}

__device__ __forceinline__ void mode_fast(const float* __restrict__ u, float2* x)
{
    #pragma unroll
    for (int g = 0; g < 6; g++) {
        float2 y[6];
        #pragma unroll
        for (int r = 0; r < 6; r++) {
            const float2* ur = (const float2*)(u + r * 6);
            float2 a = ur[0], b = ur[1], c = ur[2];
            y[r].x = a.x*x[g*6+0].x + a.y*x[g*6+1].x + b.x*x[g*6+2].x
                   + b.y*x[g*6+3].x + c.x*x[g*6+4].x + c.y*x[g*6+5].x;
            y[r].y = a.x*x[g*6+0].y + a.y*x[g*6+1].y + b.x*x[g*6+2].y
                   + b.y*x[g*6+3].y + c.x*x[g*6+4].y + c.y*x[g*6+5].y;
        }
        #pragma unroll
        for (int r = 0; r < 6; r++) x[g*6+r] = y[r];
    }
}

__device__ __forceinline__ void mode_slow(const float* __restrict__ u, float2* x)
{
    #pragma unroll
    for (int g = 0; g < 6; g++) {
        float2 y[6];
        #pragma unroll
        for (int r = 0; r < 6; r++) {
            const float2* ur = (const float2*)(u + r * 6);
            float2 a = ur[0], b = ur[1], c = ur[2];
            y[r].x = a.x*x[0*6+g].x + a.y*x[1*6+g].x + b.x*x[2*6+g].x
                   + b.y*x[3*6+g].x + c.x*x[4*6+g].x + c.y*x[5*6+g].x;
            y[r].y = a.x*x[0*6+g].y + a.y*x[1*6+g].y + b.x*x[2*6+g].y
                   + b.y*x[3*6+g].y + c.x*x[4*6+g].y + c.y*x[5*6+g].y;
        }
        #pragma unroll
        for (int r = 0; r < 6; r++) x[r*6+g] = y[r];
    }
}

__device__ __forceinline__ void phase36(const float2* __restrict__ ph, float2* x)
{
    #pragma unroll
    for (int t = 0; t < 36; t++) {
        float2 p = ph[t], v = x[t];
        x[t] = make_float2(v.x*p.x - v.y*p.y, v.x*p.y + v.y*p.x);
    }
}

extern __shared__ __align__(16) float2 sSt[];   // [MAXNS][SPAD]

__global__ __launch_bounds__(TPB, 3) void qnn_kernel(const float* __restrict__ patches,
                                                     const float* __restrict__ enc_w,
                                                     const float* __restrict__ enc_b,
                                                     const float* __restrict__ ro_w,
                                                     const float* __restrict__ ro_b,
                                                     float* __restrict__ out)
{
    __shared__ __align__(16) float  sPk[2][164];
    __shared__ __align__(16) float  sU1r[4][4][36];
    __shared__ __align__(16) float2 sPh[4][2][2][36];
    __shared__ float sAlpha[MAXNS][4];
    __shared__ float sD0[MAXNS][4][6];
    __shared__ float sPart[4 * MAXNS][37];
    __shared__ float sRed[4 * MAXNS][9];
    __shared__ float sQ[4 * MAXNS];

    int tid = threadIdx.x;
    int b = blockIdx.x;
    // blocks 0..271: 5 states; blocks 272..443: 4 states (272*5 + 172*4 = 2048)
    int cnt = (b < 272) ? 5 : 4;
    int p0  = (b < 272) ? b * 5 : 1360 + (b - 272) * 4;
    int s = tid / 36, j = tid % 36;
    bool act = s < cnt;
    float2* stS = sSt + s * SPAD;

    // one-time staging
    for (int i = tid; i < 41; i += TPB)
        ((float4*)sPk[0])[i] = __ldg((const float4*)g_BSp[0] + i);
    for (int i = tid; i < 144; i += TPB)
        ((float4*)sU1r)[i] = __ldg((const float4*)g_U1r + i);
    for (int i = tid; i < 288; i += TPB)
        ((float4*)sPh)[i] = __ldg((const float4*)g_Ph + i);

    // alpha
    {
        int w = tid >> 5, lane = tid & 31;
        if (w < 4) {
            for (int task = w; task < 4 * cnt; task += 4) {
                int ss = task >> 2, m = task & 3;
                const float* pr = patches + (size_t)(p0 + ss) * 64;
                float v = pr[lane] * enc_w[m * 64 + lane]
                        + pr[lane + 32] * enc_w[m * 64 + lane + 32];
                #pragma unroll
                for (int o = 16; o; o >>= 1) v += __shfl_xor_sync(0xffffffffu, v, o);
                if (lane == 0) sAlpha[ss][m] = v + enc_b[m];
            }
        }
    }
    __syncthreads();

    // Denc vacuum columns
    if (tid < 4 * cnt) {
        int ss = tid >> 2, m = tid & 3;
        float al = sAlpha[ss][m];
        const float S1=1.f, S2=1.41421356f, S3=1.73205081f, S4=2.f, S5=2.23606798f;
        float v0=1,v1=0,v2=0,v3=0,v4=0,v5=0;
        float t0=1,t1=0,t2=0,t3=0,t4=0,t5=0;
        for (int k = 1; k <= 28; k++) {
            float ik = al / (float)k;
            float n0 = ik * (          - S1 * t1);
            float n1 = ik * (S1 * t0 - S2 * t2);
            float n2 = ik * (S2 * t1 - S3 * t3);
            float n3 = ik * (S3 * t2 - S4 * t4);
            float n4 = ik * (S4 * t3 - S5 * t5);
            float n5 = ik * (S5 * t4);
            t0=n0;t1=n1;t2=n2;t3=n3;t4=n4;t5=n5;
            v0+=n0;v1+=n1;v2+=n2;v3+=n3;v4+=n4;v5+=n5;
        }
        sD0[ss][m][0]=v0; sD0[ss][m][1]=v1; sD0[ss][m][2]=v2;
        sD0[ss][m][3]=v3; sD0[ss][m][4]=v4; sD0[ss][m][5]=v5;
    }
    __syncthreads();

    float2 x[36];

    #define STG(K)                                                         \
        for (int i = tid; i < 41; i += TPB)                                \
            ((float4*)sPk[(K) & 1])[i] = __ldg((const float4*)g_BSp[K] + i);

    #pragma unroll 1
    for (int h = 0; h < 4; h++) {
        // ---- PASS A: tile (n0,n1); pending set h-1 mode 0,1 ops; BS01 ----
        if (h) __syncthreads();
        STG(3*h + 1)
        if (act) {
            if (h == 0) {
                float c23 = sD0[s][2][j/6] * sD0[s][3][j%6];
                #pragma unroll
                for (int a = 0; a < 6; a++) {
                    float va = sD0[s][0][a] * c23;
                    #pragma unroll
                    for (int bb = 0; bb < 6; bb++)
                        x[a*6+bb] = make_float2(va * sD0[s][1][bb], 0.f);
                }
            } else {
                #pragma unroll
                for (int t = 0; t < 36; t++) x[t] = stS[t*37 + j];
                int hs = h - 1;
                phase36(&sPh[hs][0][0][0], x);
                mode_slow(sU1r[hs][0], x);
                mode_fast(sU1r[hs][1], x);
                if (hs & 1) phase36(&sPh[hs][1][0][0], x);
            }
            bs_apply(sPk[(3*h) & 1], x);
            #pragma unroll
            for (int t = 0; t < 36; t++) stS[t*37 + j] = x[t];
        }
        __syncthreads();

        // ---- PASS B: tile (n1,n2); BS12 ----
        STG(3*h + 2)
        if (act) {
            int base = (j/6)*222 + (j%6);
            #pragma unroll
            for (int t = 0; t < 36; t++) x[t] = stS[base + (t/6)*37 + (t%6)*6];
            bs_apply(sPk[(3*h+1) & 1], x);
            #pragma unroll
            for (int t = 0; t < 36; t++) stS[base + (t/6)*37 + (t%6)*6] = x[t];
        }
        __syncthreads();

        // ---- PASS C: tile (n2,n3); BS23; set h mode 2,3 ops ----
        if (3*h + 3 < 12) { STG(3*h + 3) }
        if (act) {
            int base = j * 37;
            #pragma unroll
            for (int t = 0; t < 36; t++) x[t] = stS[base + t];
            bs_apply(sPk[(3*h+2) & 1], x);
            phase36(&sPh[h][0][1][0], x);
            mode_slow(sU1r[h][2], x);
            mode_fast(sU1r[h][3], x);
            if (h & 1) phase36(&sPh[h][1][1][0], x);
            #pragma unroll
            for (int t = 0; t < 36; t++) stS[base + t] = x[t];
        }
    }

    // ---- EPILOGUE: set 3 mode 0,1 ops; quadratures ----
    __syncthreads();
    const float W[5] = {2.f, 2.82842712f, 3.46410162f, 4.f, 4.47213595f};
    if (act) {
        #pragma unroll
        for (int t = 0; t < 36; t++) x[t] = stS[t*37 + j];
        phase36(&sPh[3][0][0][0], x);
        mode_slow(sU1r[3][0], x);
        mode_fast(sU1r[3][1], x);
        phase36(&sPh[3][1][0][0], x);

        float q0 = 0.f, q1 = 0.f;
        #pragma unroll
        for (int a = 0; a < 6; a++)
            #pragma unroll
            for (int bb = 0; bb < 6; bb++) {
                if (a < 5)  q0 += W[a]  * (x[a*6+bb].x * x[(a+1)*6+bb].x + x[a*6+bb].y * x[(a+1)*6+bb].y);
                if (bb < 5) q1 += W[bb] * (x[a*6+bb].x * x[a*6+bb+1].x + x[a*6+bb].y * x[a*6+bb+1].y);
            }
        sPart[s*4 + 0][j] = q0; sPart[s*4 + 1][j] = q1;
        #pragma unroll
        for (int t = 0; t < 36; t++) stS[t*37 + j] = x[t];
    }
    __syncthreads();

    if (act) {
        float q2 = 0.f, q3 = 0.f;
        int n2 = j / 6, n3 = j % 6;
        #pragma unroll
        for (int t = 0; t < 36; t++) {
            int base = t*37 + j;
            float2 s0 = stS[base];
            if (n2 < 5) { float2 sN = stS[base + 6]; q2 += s0.x*sN.x + s0.y*sN.y; }
            if (n3 < 5) { float2 sN = stS[base + 1]; q3 += s0.x*sN.x + s0.y*sN.y; }
        }
        if (n2 < 5) q2 *= W[n2];
        if (n3 < 5) q3 *= W[n3];
        sPart[s*4 + 2][j] = q2; sPart[s*4 + 3][j] = q3;
    }
    __syncthreads();

    {
        int row = tid / 9, col = tid % 9;     // 180 = 20 rows x 9 cols exactly
        if (row < 4 * cnt) {
            float acc = 0.f;
            #pragma unroll
            for (int k = 0; k < 4; k++) acc += sPart[row][col*4 + k];
            sRed[row][col] = acc;
        }
    }
    __syncthreads();
    if (tid < 4 * cnt) {
        float acc = 0.f;
        #pragma unroll
        for (int k = 0; k < 9; k++) acc += sRed[tid][k];
        sQ[tid] = acc;
    }
    __syncthreads();

    for (int idx = tid; idx < cnt * DD; idx += TPB) {
        int ss = idx >> 6, d = idx & 63;
        float o = ro_b[d];
        #pragma unroll
        for (int m = 0; m < 4; m++) o = fmaf(sQ[ss*4 + m], ro_w[d*4 + m], o);
        out[(size_t)(p0 + ss) * DD + d] = o;
    }
}

extern "C" void kernel_launch(void* const* d_in, const int* in_sizes, int n_in,
                              void* d_out, int out_size)
{
    const float* patches = (const float*)d_in[0];
    const float* enc_w   = (const float*)d_in[1];
    const float* enc_b   = (const float*)d_in[2];
    const float* bs1     = (const float*)d_in[3];
    const float* rot1    = (const float*)d_in[4];
    const float* sq_r    = (const float*)d_in[5];
    const float* bs2     = (const float*)d_in[6];
    const float* rot2    = (const float*)d_in[7];
    const float* disp    = (const float*)d_in[8];
    const float* kerr    = (const float*)d_in[9];
    const float* ro_w    = (const float*)d_in[10];
    const float* ro_b    = (const float*)d_in[11];

    // opt-in for >48KB combined smem (static ~17KB + dynamic 53.3KB)
    static bool attr_set = false;
    if (!attr_set) {
        cudaFuncSetAttribute(qnn_kernel, cudaFuncAttributeMaxDynamicSharedMemorySize,
                             MAXNS * SPAD * (int)sizeof(float2));
        attr_set = true;
    }

    precompute_kernel<<<1, 148>>>(bs1, sq_r, bs2, disp, rot1, rot2, kerr);
    qnn_kernel<<<GRID, TPB, MAXNS * SPAD * sizeof(float2)>>>(
        patches, enc_w, enc_b, ro_w, ro_b, (float*)d_out);
}